// round 6
// baseline (speedup 1.0000x reference)
#include <cuda_runtime.h>
#include <cstdint>

#define MAX_SEG 100001
#define SEGS_PER_BLOCK 4
#define SMEM_IDX 1024   // indices staged per block (4 segments, mean ~51 edges)

// scratch (no cudaMalloc allowed)
__device__ int g_offsets[MAX_SEG + 1];

// ---------------------------------------------------------------------------
// Packed-f32 helpers (sm_103a f32x2 pipe) + raw 64-bit global load.
// ---------------------------------------------------------------------------
__device__ __forceinline__ unsigned long long ldg_b64(const void* p) {
    unsigned long long v;
    asm volatile("ld.global.nc.b64 %0, [%1];" : "=l"(v) : "l"(p));
    return v;
}
__device__ __forceinline__ unsigned long long addf32x2(unsigned long long a,
                                                       unsigned long long b) {
    unsigned long long r;
    asm("add.rn.f32x2 %0, %1, %2;" : "=l"(r) : "l"(a), "l"(b));
    return r;
}

// ---------------------------------------------------------------------------
// Inline dtype detection (reference declares int64; JAX w/o x64 emits int32).
// For little-endian int64 indices in [0, 2^31), every odd int32 word is 0.
// For int32 data those words are uniform random gather indices;
// P(first 8 all zero) ~ 1e-42. One broadcast sector load + one vote.
// ---------------------------------------------------------------------------
__device__ __forceinline__ bool detect_is64_warp(const void* gidx, int lane) {
    const int* p = (const int*)gidx;
    int w = (lane < 8) ? p[2 * lane + 1] : 0;
    return __all_sync(0xFFFFFFFFu, w == 0);
}

__device__ __forceinline__ int load_idx(const void* p, int i, bool is64) {
    return is64 ? (int)((const long long*)p)[i] : ((const int*)p)[i];
}

// ---------------------------------------------------------------------------
// CSR offsets from sorted segment ids. offsets[s] = first edge with seg >= s.
// ---------------------------------------------------------------------------
__global__ void build_offsets_kernel(const void* __restrict__ seg,
                                     const void* __restrict__ gidx,
                                     int E, int nseg) {
    int e = blockIdx.x * blockDim.x + threadIdx.x;
    bool is64 = detect_is64_warp(gidx, threadIdx.x & 31);
    if (e >= E) return;
    int cur = load_idx(seg, e, is64);
    int prev = (e == 0) ? -1 : load_idx(seg, e - 1, is64);
    for (int s = prev + 1; s <= cur; s++) g_offsets[s] = e;
    if (e == E - 1) {
        for (int s = cur + 1; s <= nseg; s++) g_offsets[s] = E;
    }
}

// ---------------------------------------------------------------------------
// Block = 4 warps = 4 consecutive segments (contiguous edge range, ids are
// sorted). Block stages all its gather indices into smem with one coalesced
// sweep. Row loop per warp: lane owns a float2 slice of the 256B row.
// Hot loop per 4 edges: 1 LDS.128 (broadcast int4 of indices) + 4 IMAD.WIDE
// + 4 LDG.64 + 4 ADD.F32X2  (~3.25 instr/edge), 4 independent 256B row reads
// in flight.
// ---------------------------------------------------------------------------
__global__ void __launch_bounds__(128)
seg_mean_kernel(const float* __restrict__ values,
                const void* __restrict__ gidx,
                float* __restrict__ out, int nseg) {
    __shared__ int s_idx[SMEM_IDX];
    __shared__ int s_off[SEGS_PER_BLOCK + 1];

    int tid  = threadIdx.x;
    int lane = tid & 31;
    int w    = tid >> 5;
    int seg0 = blockIdx.x * SEGS_PER_BLOCK;
    bool is64 = detect_is64_warp(gidx, lane);

    if (tid <= SEGS_PER_BLOCK) {
        int s = seg0 + tid;
        s_off[tid] = g_offsets[s < nseg ? s : nseg];
    }
    __syncthreads();

    int estart = s_off[0];
    int etot   = s_off[SEGS_PER_BLOCK] - estart;
    int nsm    = etot < SMEM_IDX ? etot : SMEM_IDX;

    // coalesced stage of all block indices into smem (int64 -> int32 on load)
    for (int i = tid; i < nsm; i += 128)
        s_idx[i] = load_idx(gidx, estart + i, is64);
    __syncthreads();

    int seg = seg0 + w;
    if (seg >= nseg) return;

    int start = s_off[w]     - estart;   // block-local edge range
    int end   = s_off[w + 1] - estart;
    int n     = end - start;

    const char* vb = (const char*)values + lane * 8;  // lane's float2 slot

    unsigned long long A0 = 0ull, A1 = 0ull, A2 = 0ull, A3 = 0ull;

    if (end <= nsm) {
        int e = start;
        // scalar prologue until e is 16B-aligned in s_idx
        int pre = (4 - (e & 3)) & 3;
        if (pre > n) pre = n;
        for (int k = 0; k < pre; k++, e++) {
            unsigned long long v = ldg_b64(vb + (unsigned)s_idx[e] * 256u);
            A0 = addf32x2(A0, v);
        }
        // main: 4 edges per iteration, one vector LDS for the indices
        for (; e + 4 <= end; e += 4) {
            int4 I = *(const int4*)&s_idx[e];
            unsigned long long v0 = ldg_b64(vb + (unsigned)I.x * 256u);
            unsigned long long v1 = ldg_b64(vb + (unsigned)I.y * 256u);
            unsigned long long v2 = ldg_b64(vb + (unsigned)I.z * 256u);
            unsigned long long v3 = ldg_b64(vb + (unsigned)I.w * 256u);
            A0 = addf32x2(A0, v0);
            A1 = addf32x2(A1, v1);
            A2 = addf32x2(A2, v2);
            A3 = addf32x2(A3, v3);
        }
        // scalar tail
        for (; e < end; e++) {
            unsigned long long v = ldg_b64(vb + (unsigned)s_idx[e] * 256u);
            A0 = addf32x2(A0, v);
        }
    } else {
        // overflow fallback (essentially never taken): idx straight from gmem
        for (int e = start; e < end; e++) {
            int i0 = (e < nsm) ? s_idx[e] : load_idx(gidx, estart + e, is64);
            unsigned long long v = ldg_b64(vb + (unsigned)i0 * 256u);
            A0 = addf32x2(A0, v);
        }
    }

    unsigned long long S = addf32x2(addf32x2(A0, A1), addf32x2(A2, A3));

    float sx = __uint_as_float((unsigned)(S & 0xFFFFFFFFull));
    float sy = __uint_as_float((unsigned)(S >> 32));

    float inv = 1.0f / (float)(n > 0 ? n : 1);
    float2 r = {sx * inv, sy * inv};
    ((float2*)(out + (long long)seg * 64))[lane] = r;
}

// ---------------------------------------------------------------------------
// launch
// inputs: 0=values [N_SRC,64] f32, 1=gather_idx [E] i64/i32,
//         2=segment_ids [E] i64/i32 (sorted), 3=num_segments (scalar, unused)
// out: [nseg,64] f32, nseg = out_size/64
// ---------------------------------------------------------------------------
extern "C" void kernel_launch(void* const* d_in, const int* in_sizes, int n_in,
                              void* d_out, int out_size) {
    const float* values = (const float*)d_in[0];
    const void*  gidx   = d_in[1];
    const void*  seg    = d_in[2];
    float* out = (float*)d_out;

    int E    = in_sizes[1];
    int nseg = out_size / 64;
    if (nseg > MAX_SEG) nseg = MAX_SEG;

    int bthreads = 256;
    build_offsets_kernel<<<(E + bthreads - 1) / bthreads, bthreads>>>(seg, gidx, E, nseg);

    int blocks = (nseg + SEGS_PER_BLOCK - 1) / SEGS_PER_BLOCK;
    seg_mean_kernel<<<blocks, 128>>>(values, gidx, out, nseg);
}